// round 3
// baseline (speedup 1.0000x reference)
#include <cuda_runtime.h>
#include <cstdint>

// Problem constants (fixed by the dataset)
#define BH      32            // B*H
#define M_DIM   2048
#define K_DIM   2048
#define N_DIM   64
#define NSEG    (BH * M_DIM)  // 65536 output rows
#define NQ      4             // k-quarters (512 rows each)
#define QROWS   (K_DIM / NQ)  // 512
#define NBIN    (NSEG * NQ)   // 262144 sub-bins
#define CAPQ    64            // per-sub-bin capacity (Poisson(16): P(any overflow) ~ 2e-18)

typedef unsigned long long ull;

__device__ unsigned g_cnt[NBIN];                       // 1 MB
__device__ ull      g_slots[(size_t)NBIN * CAPQ];      // 128 MB

__global__ void zero_counts_kernel() {
    int i = blockIdx.x * blockDim.x + threadIdx.x;     // uint4 index
    if (i < NBIN / 4)
        reinterpret_cast<uint4*>(g_cnt)[i] = make_uint4(0u, 0u, 0u, 0u);
}

// 4 nonzeros per thread, vectorized index/value loads.
__global__ void bin_kernel(const float* __restrict__ values,
                           const int*   __restrict__ idx_bh,
                           const int*   __restrict__ idx_m,
                           const int*   __restrict__ idx_k,
                           int nnz) {
    int g = blockIdx.x * blockDim.x + threadIdx.x;
    int base = g * 4;
    if (base >= nnz) return;

    if (base + 3 < nnz) {
        int4   bh4 = *reinterpret_cast<const int4*>(idx_bh + base);
        int4   m4  = *reinterpret_cast<const int4*>(idx_m  + base);
        int4   k4  = *reinterpret_cast<const int4*>(idx_k  + base);
        float4 v4  = *reinterpret_cast<const float4*>(values + base);

        int   bhs[4] = {bh4.x, bh4.y, bh4.z, bh4.w};
        int   ms[4]  = {m4.x,  m4.y,  m4.z,  m4.w};
        int   ks[4]  = {k4.x,  k4.y,  k4.z,  k4.w};
        float vs[4]  = {v4.x,  v4.y,  v4.z,  v4.w};

        #pragma unroll
        for (int j = 0; j < 4; j++) {
            int k   = ks[j];
            int bin = (bhs[j] * M_DIM + ms[j]) * NQ + (k >> 9);
            unsigned pos = atomicAdd(&g_cnt[bin], 1u);
            if (pos < CAPQ) {
                g_slots[(size_t)bin * CAPQ + pos] =
                    ((ull)(unsigned)(k & (QROWS - 1)) << 32) |
                    (ull)__float_as_uint(vs[j]);
            }
        }
    } else {
        for (int j = 0; j < 4 && base + j < nnz; j++) {
            int k   = idx_k[base + j];
            int bin = (idx_bh[base + j] * M_DIM + idx_m[base + j]) * NQ + (k >> 9);
            unsigned pos = atomicAdd(&g_cnt[bin], 1u);
            if (pos < CAPQ) {
                g_slots[(size_t)bin * CAPQ + pos] =
                    ((ull)(unsigned)(k & (QROWS - 1)) << 32) |
                    (ull)__float_as_uint(values[base + j]);
            }
        }
    }
}

// 128 CTAs = (bh 32) x (m-chunk 4). 1024 threads. 128 KB smem caches one
// 512-row b-quarter; warps accumulate 16 segments each in registers across
// the 4 quarters; single coalesced store per segment at the end.
__global__ void __launch_bounds__(1024, 1)
reduce_kernel(const float* __restrict__ bmat,
              float*       __restrict__ out) {
    extern __shared__ float2 sB[];          // [512 rows][32 float2] = 128 KB

    int bh   = blockIdx.x >> 2;
    int mc   = blockIdx.x & 3;
    int tid  = threadIdx.x;
    int wid  = tid >> 5;                    // 0..31
    int lane = tid & 31;                    // column pair: floats [lane*2, lane*2+1]

    int m0  = mc * (M_DIM / 4) + wid * 16;  // first of this warp's 16 segments
    int seg0 = bh * M_DIM + m0;

    float2 acc[16];
    #pragma unroll
    for (int s = 0; s < 16; s++) acc[s] = make_float2(0.f, 0.f);

    for (int q = 0; q < NQ; q++) {
        // ---- fill smem with b[bh, q*512:(q+1)*512, :] ----
        {
            const float4* gB = reinterpret_cast<const float4*>(bmat) +
                               ((size_t)bh * K_DIM + (size_t)q * QROWS) * (N_DIM / 4);
            float4* sB4 = reinterpret_cast<float4*>(sB);
            #pragma unroll
            for (int t = 0; t < 8; t++)            // 8192 float4 / 1024 threads
                sB4[tid + t * 1024] = __ldg(gB + tid + t * 1024);
        }
        __syncthreads();

        // ---- accumulate this quarter's nonzeros for the warp's 16 segments ----
        #pragma unroll 1
        for (int s = 0; s < 16; s++) {
            int bin = (seg0 + s) * NQ + q;
            int cnt = (int)min(g_cnt[bin], (unsigned)CAPQ);
            const ull* sl = g_slots + (size_t)bin * CAPQ;
            float2 a = acc[s];

            int j = 0;
            for (; j + 2 <= cnt; j += 2) {
                ulonglong2 p = *reinterpret_cast<const ulonglong2*>(sl + j);
                int   k0 = (int)(p.x >> 32);
                float v0 = __uint_as_float((unsigned)p.x);
                int   k1 = (int)(p.y >> 32);
                float v1 = __uint_as_float((unsigned)p.y);
                float2 b0 = sB[k0 * 32 + lane];
                float2 b1 = sB[k1 * 32 + lane];
                a.x += v0 * b0.x; a.y += v0 * b0.y;
                a.x += v1 * b1.x; a.y += v1 * b1.y;
            }
            if (j < cnt) {
                ull p = sl[j];
                int   k = (int)(p >> 32);
                float v = __uint_as_float((unsigned)p);
                float2 bv = sB[k * 32 + lane];
                a.x += v * bv.x; a.y += v * bv.y;
            }
            acc[s] = a;
        }
        __syncthreads();                     // smem reused next quarter
    }

    // ---- write out: 16 rows, 256 B coalesced per row ----
    #pragma unroll
    for (int s = 0; s < 16; s++) {
        float2* dst = reinterpret_cast<float2*>(out + (size_t)(seg0 + s) * N_DIM) + lane;
        *dst = acc[s];
    }
}

extern "C" void kernel_launch(void* const* d_in, const int* in_sizes, int n_in,
                              void* d_out, int out_size) {
    const float* values = (const float*)d_in[0];
    const float* bmat   = (const float*)d_in[1];
    const int*   idx_bh = (const int*)d_in[2];
    const int*   idx_m  = (const int*)d_in[3];
    const int*   idx_k  = (const int*)d_in[4];
    float*       out    = (float*)d_out;

    int nnz = in_sizes[0];

    // opt into 128 KB dynamic smem for the reduce kernel (idempotent)
    cudaFuncSetAttribute(reduce_kernel,
                         cudaFuncAttributeMaxDynamicSharedMemorySize, 131072);

    // 1) reset sub-bin cursors (uint4 stores)
    zero_counts_kernel<<<(NBIN / 4 + 255) / 256, 256>>>();

    // 2) bin nonzeros by (segment, k-quarter)
    {
        int groups = (nnz + 3) / 4;
        bin_kernel<<<(groups + 255) / 256, 256>>>(values, idx_bh, idx_m, idx_k, nnz);
    }

    // 3) smem-cached segmented reduction; no atomics, plain stores
    reduce_kernel<<<BH * 4, 1024, 131072>>>(bmat, out);
}